// round 16
// baseline (speedup 1.0000x reference)
#include <cuda_runtime.h>
#include <math.h>

#define NH 2
#define NB 2048
#define NM 64
#define ND 16
#define NREL 32

// Fused kernel: 512 blocks x 512 threads; each block handles 4 b's.
// Phase A (threads 0-127, R14-proven): each relm float4 load feeds 4 bb accums.
// Phase B: four independent quarter-blocks of 128 threads, each owning one b:
//          quad-split 4-pass gathers + own softmax (R3/R7-proven structure).
__global__ __launch_bounds__(512)
void ripple_fused_kernel(const int* __restrict__ items,
                         const int* __restrict__ heads,
                         const int* __restrict__ rels,
                         const int* __restrict__ tails,
                         const float* __restrict__ ent,
                         const float* __restrict__ relm,
                         float* __restrict__ out)
{
    const int b0   = blockIdx.x * 4;
    const int t    = threadIdx.x;      // 0..511
    const int qb   = t >> 7;           // quarter-block 0..3 -> owns b0+qb
    const int tl   = t & 127;          // thread-in-quarter
    const int lane = t & 31;
    const int widq = tl >> 5;          // warp-in-quarter 0..3
    const int sub  = t & 3;
    const int quad = tl >> 2;          // 0..31

    __shared__ __align__(16) float  item_s[4][ND];
    __shared__ __align__(16) float4 q_s[4][NREL * 4];   // [bb][r*4+jg]
    __shared__ float logit_s[4][NH * NM];
    __shared__ float td_s[4][NH * NM];
    __shared__ float red_s[4][8];

    // ---- Phase A0: load 4 item embeddings (64 floats) ----
    if (t < 4 * ND) {
        const int ib = t >> 4;
        const int d  = t & 15;
        item_s[ib][d] = ent[(size_t)items[b0 + ib] * ND + d];
    }
    __syncthreads();

    // ---- Phase A1: q-precompute; threads 0-127, 4 accumulators per relm load ----
    if (t < 128) {
        const int r  = t >> 2;
        const int jg = t & 3;
        const float4* relm4 = (const float4*)relm;

        float4 a0 = make_float4(0.f, 0.f, 0.f, 0.f);
        float4 a1 = make_float4(0.f, 0.f, 0.f, 0.f);
        float4 a2 = make_float4(0.f, 0.f, 0.f, 0.f);
        float4 a3 = make_float4(0.f, 0.f, 0.f, 0.f);
        #pragma unroll
        for (int i = 0; i < ND; i++) {
            float4 Rv = relm4[r * 64 + i * 4 + jg];   // R[r][i][jg*4..+3]
            float s0 = item_s[0][i];
            float s1 = item_s[1][i];
            float s2 = item_s[2][i];
            float s3 = item_s[3][i];
            a0.x += s0 * Rv.x; a0.y += s0 * Rv.y; a0.z += s0 * Rv.z; a0.w += s0 * Rv.w;
            a1.x += s1 * Rv.x; a1.y += s1 * Rv.y; a1.z += s1 * Rv.z; a1.w += s1 * Rv.w;
            a2.x += s2 * Rv.x; a2.y += s2 * Rv.y; a2.z += s2 * Rv.z; a2.w += s2 * Rv.w;
            a3.x += s3 * Rv.x; a3.y += s3 * Rv.y; a3.z += s3 * Rv.z; a3.w += s3 * Rv.w;
        }
        q_s[0][t] = a0;    // t == r*4+jg
        q_s[1][t] = a1;
        q_s[2][t] = a2;
        q_s[3][t] = a3;
    }
    __syncthreads();

    const float4* ent4 = (const float4*)ent;
    const int     b    = b0 + qb;
    const float4  iv   = ((const float4*)item_s[qb])[sub];

    // ---- Phase B1: 4 quad-split passes for this quarter's b ----
    #pragma unroll
    for (int pass = 0; pass < 4; pass++) {
        const int s    = pass * 32 + quad;       // slot 0..127
        const int hop  = s >> 6;
        const int m    = s & 63;
        const int gidx = hop * (NB * NM) + b * NM + m;

        const int hidx = heads[gidx];
        const int ridx = rels[gidx];
        const int tidx = tails[gidx];

        float4 hv = ent4[(size_t)hidx * 4 + sub];
        float4 tv = ent4[(size_t)tidx * 4 + sub];
        float4 qv = q_s[qb][ridx * 4 + sub];

        float pl = qv.x * hv.x + qv.y * hv.y + qv.z * hv.z + qv.w * hv.w;
        float pt = iv.x * tv.x + iv.y * tv.y + iv.z * tv.z + iv.w * tv.w;

        pl += __shfl_xor_sync(0xffffffffu, pl, 1);
        pl += __shfl_xor_sync(0xffffffffu, pl, 2);
        pt += __shfl_xor_sync(0xffffffffu, pt, 1);
        pt += __shfl_xor_sync(0xffffffffu, pt, 2);

        logit_s[qb][s] = pl;
        td_s[qb][s]    = pt;
    }
    __syncthreads();

    // ---- Phase B2: softmax per quarter; thread tl owns slot tl ----
    const int hop = tl >> 6;
    float logit = logit_s[qb][tl];
    float td    = td_s[qb][tl];

    float mx = logit;
    #pragma unroll
    for (int o = 16; o > 0; o >>= 1)
        mx = fmaxf(mx, __shfl_xor_sync(0xffffffffu, mx, o));
    if (lane == 0) red_s[qb][widq] = mx;
    __syncthreads();
    mx = fmaxf(red_s[qb][hop * 2], red_s[qb][hop * 2 + 1]);

    float e = __expf(logit - mx);
    float sm = e;
    #pragma unroll
    for (int o = 16; o > 0; o >>= 1)
        sm += __shfl_xor_sync(0xffffffffu, sm, o);
    if (lane == 0) red_s[qb][4 + widq] = sm;
    __syncthreads();
    sm = red_s[qb][4 + hop * 2] + red_s[qb][4 + hop * 2 + 1];

    const float pi = e / sm;

    // ---- contribution: pi * (tail . item); reduce over this quarter's 128 threads ----
    float c = pi * td;
    #pragma unroll
    for (int o = 16; o > 0; o >>= 1)
        c += __shfl_xor_sync(0xffffffffu, c, o);
    __syncthreads();                 // protect red_s reuse
    if (lane == 0) red_s[qb][widq] = c;
    __syncthreads();

    if (tl == 0) {
        float total = red_s[qb][0] + red_s[qb][1] + red_s[qb][2] + red_s[qb][3];
        out[b] = 1.f / (1.f + __expf(-total));
    }
}

extern "C" void kernel_launch(void* const* d_in, const int* in_sizes, int n_in,
                              void* d_out, int out_size)
{
    const int*   items = (const int*)d_in[0];
    const int*   heads = (const int*)d_in[1];
    const int*   rels  = (const int*)d_in[2];
    const int*   tails = (const int*)d_in[3];
    const float* ent   = (const float*)d_in[4];
    const float* relm  = (const float*)d_in[5];
    float*       out   = (float*)d_out;

    ripple_fused_kernel<<<NB / 4, 512>>>(items, heads, rels, tails, ent, relm, out);
}